// round 6
// baseline (speedup 1.0000x reference)
#include <cuda_runtime.h>
#include <math.h>
#include <stdint.h>

#define B_  2
#define N_  1024
#define M_  1024
#define C_  1024
#define H_  16
#define P_  4

// scale/P = (1/sqrt(8))/4
#define QW_BASE 0.088388347648318447f

#define QROWS    32
#define SSTRIDE  1036              // words; mod 32 = 12 -> conflict-free frag loads
#define KVSTRIDE 68
#define KVBUF    (64 * KVSTRIDE)
#define SMEM_ATTN ((QROWS * SSTRIDE + 2 * KVBUF) * 4)

// ---------------- device scratch (statics: allocation-free rule) ----------------
__device__ float g_Qw[B_ * N_ * C_];
__device__ float g_K [B_ * M_ * C_];
__device__ float g_V [B_ * M_ * C_];
__device__ float g_AO[B_ * N_ * C_];
__device__ float g_probs_fb[(size_t)B_ * H_ * N_ * M_];

// ---------------- tf32 helpers ---------------------------------------------------
__device__ __forceinline__ uint32_t f2tf(float x) {
    uint32_t r;
    asm("cvt.rna.tf32.f32 %0, %1;" : "=r"(r) : "f"(x));
    return r;
}
__device__ __forceinline__ void mma8(float* c, const uint32_t* a, const uint32_t* b) {
    asm volatile(
        "mma.sync.aligned.m16n8k8.row.col.f32.tf32.tf32.f32 "
        "{%0,%1,%2,%3},{%4,%5,%6,%7},{%8,%9},{%0,%1,%2,%3};"
        : "+f"(c[0]), "+f"(c[1]), "+f"(c[2]), "+f"(c[3])
        : "r"(a[0]), "r"(a[1]), "r"(a[2]), "r"(a[3]), "r"(b[0]), "r"(b[1]));
}

// ---------------- TF32 GEMM: C = A[MxK] @ B[KxN] + bias (+ Q-weight epilogue) -----
// BM=BN=128, BK=16, 256 threads (8 warps, 2m x 4n), warp tile 64x32.
__global__ __launch_bounds__(256) void sgemm_tc(
    const float* __restrict__ A, const float* __restrict__ Bm,
    const float* __restrict__ bias, float* __restrict__ Cm,
    int M, int N, int K, int epi, const float* __restrict__ lamlog)
{
    __shared__ uint32_t As[128][20];   // [m][k], stride 20 (bank-safe: 20*grp+t4)
    __shared__ uint32_t Bs[16][136];   // [k][n], stride 136 (bank-safe: 8*t4+grp)

    const int tid  = threadIdx.x;
    const int warp = tid >> 5, lane = tid & 31;
    const int grp  = lane >> 2, t4 = lane & 3;
    const int wm   = warp >> 2;      // 0..1 -> 64 rows
    const int wn   = warp & 3;       // 0..3 -> 32 cols
    const int row0 = blockIdx.y * 128;
    const int col0 = blockIdx.x * 128;

    float acc[4][4][4] = {};

    for (int k0 = 0; k0 < K; k0 += 16) {
        // stage A tile 128x16 (row-major, cvt to tf32)
#pragma unroll
        for (int i = 0; i < 2; i++) {
            int t  = tid * 2 + i;
            int ar = t >> 2, ac4 = t & 3;
            float4 v = *reinterpret_cast<const float4*>(
                A + (size_t)(row0 + ar) * K + k0 + ac4 * 4);
            As[ar][ac4 * 4 + 0] = f2tf(v.x);
            As[ar][ac4 * 4 + 1] = f2tf(v.y);
            As[ar][ac4 * 4 + 2] = f2tf(v.z);
            As[ar][ac4 * 4 + 3] = f2tf(v.w);
        }
        // stage B tile 16x128
#pragma unroll
        for (int i = 0; i < 2; i++) {
            int t  = tid * 2 + i;
            int br = t >> 5, bc4 = t & 31;
            float4 v = *reinterpret_cast<const float4*>(
                Bm + (size_t)(k0 + br) * N + col0 + bc4 * 4);
            Bs[br][bc4 * 4 + 0] = f2tf(v.x);
            Bs[br][bc4 * 4 + 1] = f2tf(v.y);
            Bs[br][bc4 * 4 + 2] = f2tf(v.z);
            Bs[br][bc4 * 4 + 3] = f2tf(v.w);
        }
        __syncthreads();

#pragma unroll
        for (int ks = 0; ks < 16; ks += 8) {
            uint32_t a[4][4], b[4][2];
#pragma unroll
            for (int i = 0; i < 4; i++) {
                int mb = wm * 64 + i * 16;
                a[i][0] = As[mb + grp][ks + t4];
                a[i][1] = As[mb + 8 + grp][ks + t4];
                a[i][2] = As[mb + grp][ks + 4 + t4];
                a[i][3] = As[mb + 8 + grp][ks + 4 + t4];
            }
#pragma unroll
            for (int j = 0; j < 4; j++) {
                int nb = wn * 32 + j * 8;
                b[j][0] = Bs[ks + t4][nb + grp];
                b[j][1] = Bs[ks + 4 + t4][nb + grp];
            }
#pragma unroll
            for (int i = 0; i < 4; i++)
#pragma unroll
                for (int j = 0; j < 4; j++)
                    mma8(acc[i][j], a[i], b[j]);
        }
        __syncthreads();
    }

    // epilogue: per-j column weight (each j covers one 8-col signal block)
    float wj[4];
#pragma unroll
    for (int j = 0; j < 4; j++) {
        if (epi) {
            int cb = col0 + wn * 32 + j * 8;
            int h = cb >> 6, s = (cb >> 3) & 7, p = s >> 1;
            wj[j] = (s & 1) ? (-QW_BASE * expf(lamlog[h * P_ + p])) : QW_BASE;
        } else {
            wj[j] = 1.0f;
        }
    }
#pragma unroll
    for (int i = 0; i < 4; i++) {
        int r0 = row0 + wm * 64 + i * 16 + grp;
#pragma unroll
        for (int j = 0; j < 4; j++) {
            int c = col0 + wn * 32 + j * 8 + 2 * t4;
            float b0 = bias[c], b1 = bias[c + 1];
            float2 v0 = make_float2((acc[i][j][0] + b0) * wj[j],
                                    (acc[i][j][1] + b1) * wj[j]);
            float2 v1 = make_float2((acc[i][j][2] + b0) * wj[j],
                                    (acc[i][j][3] + b1) * wj[j]);
            *reinterpret_cast<float2*>(Cm + (size_t)r0 * N + c)       = v0;
            *reinterpret_cast<float2*>(Cm + (size_t)(r0 + 8) * N + c) = v1;
        }
    }
}

// ---------------- fused attention: S=Q'K^T -> softmax -> probs out -> P@V ---------
// Block = (b, h, 32 q-rows). S row-block resident in smem. 256 threads / 8 warps.
__global__ __launch_bounds__(256, 1) void attn_fused(float* __restrict__ probs)
{
    extern __shared__ uint32_t sm[];
    float*    S  = reinterpret_cast<float*>(sm);      // [QROWS][SSTRIDE] fp32 scores
    uint32_t* St = sm;                                 // tf32 view after softmax
    uint32_t* KV = sm + QROWS * SSTRIDE;               // [2][64][KVSTRIDE]

    const int tid  = threadIdx.x;
    const int warp = tid >> 5, lane = tid & 31;
    const int grp  = lane >> 2, t4 = lane & 3;
    const int nt = blockIdx.x, h = blockIdx.y, b = blockIdx.z;
    const int n0 = nt * QROWS;

    // ---- stage Q tile (32x64) into KV[0], preload A-frags to registers ----------
#pragma unroll
    for (int i = 0; i < 2; i++) {
        int t = tid + i * 256;
        int r = t >> 4, c4 = t & 15;
        float4 v = *reinterpret_cast<const float4*>(
            g_Qw + (size_t)(b * N_ + n0 + r) * C_ + h * 64 + c4 * 4);
        KV[r * KVSTRIDE + c4 * 4 + 0] = f2tf(v.x);
        KV[r * KVSTRIDE + c4 * 4 + 1] = f2tf(v.y);
        KV[r * KVSTRIDE + c4 * 4 + 2] = f2tf(v.z);
        KV[r * KVSTRIDE + c4 * 4 + 3] = f2tf(v.w);
    }
    __syncthreads();

    uint32_t qa[8][2][4];
#pragma unroll
    for (int ks = 0; ks < 8; ks++) {
        int k = ks * 8;
#pragma unroll
        for (int hf = 0; hf < 2; hf++) {
            int rb = hf * 16;
            qa[ks][hf][0] = KV[(rb + grp) * KVSTRIDE + k + t4];
            qa[ks][hf][1] = KV[(rb + 8 + grp) * KVSTRIDE + k + t4];
            qa[ks][hf][2] = KV[(rb + grp) * KVSTRIDE + k + 4 + t4];
            qa[ks][hf][3] = KV[(rb + 8 + grp) * KVSTRIDE + k + 4 + t4];
        }
    }
    __syncthreads();   // Q frags captured; KV buffers free

    // ---- phase 1: S = Q' K^T, K tiles double-buffered ---------------------------
    {
        const float* ksrc = g_K + (size_t)(b * M_) * C_ + h * 64;
        // stage K tile 0
#pragma unroll
        for (int i = 0; i < 4; i++) {
            int t = tid + i * 256;
            int r = t >> 4, c4 = t & 15;
            float4 v = *reinterpret_cast<const float4*>(ksrc + (size_t)r * C_ + c4 * 4);
            uint32_t* d = KV + r * KVSTRIDE + c4 * 4;
            d[0] = f2tf(v.x); d[1] = f2tf(v.y); d[2] = f2tf(v.z); d[3] = f2tf(v.w);
        }
        __syncthreads();

        for (int mt = 0; mt < 16; mt++) {
            if (mt < 15) {
                const float* s2 = ksrc + (size_t)((mt + 1) * 64) * C_;
                uint32_t* dst = KV + ((mt + 1) & 1) * KVBUF;
#pragma unroll
                for (int i = 0; i < 4; i++) {
                    int t = tid + i * 256;
                    int r = t >> 4, c4 = t & 15;
                    float4 v = *reinterpret_cast<const float4*>(s2 + (size_t)r * C_ + c4 * 4);
                    uint32_t* d = dst + r * KVSTRIDE + c4 * 4;
                    d[0] = f2tf(v.x); d[1] = f2tf(v.y); d[2] = f2tf(v.z); d[3] = f2tf(v.w);
                }
            }
            const uint32_t* Kb = KV + (mt & 1) * KVBUF;
            const int mb = warp * 8;
            float acc[2][4] = {};
#pragma unroll
            for (int ks = 0; ks < 8; ks++) {
                uint32_t bb[2];
                bb[0] = Kb[(mb + grp) * KVSTRIDE + ks * 8 + t4];
                bb[1] = Kb[(mb + grp) * KVSTRIDE + ks * 8 + 4 + t4];
                mma8(acc[0], qa[ks][0], bb);
                mma8(acc[1], qa[ks][1], bb);
            }
            int col = mt * 64 + warp * 8 + 2 * t4;
#pragma unroll
            for (int hf = 0; hf < 2; hf++) {
                int r0 = hf * 16 + grp;
                *reinterpret_cast<float2*>(&S[r0 * SSTRIDE + col]) =
                    make_float2(acc[hf][0], acc[hf][1]);
                *reinterpret_cast<float2*>(&S[(r0 + 8) * SSTRIDE + col]) =
                    make_float2(acc[hf][2], acc[hf][3]);
            }
            __syncthreads();
        }
    }

    // ---- phase 2: row softmax; write probs; re-store P as tf32 in S -------------
#pragma unroll
    for (int j = 0; j < 4; j++) {
        int r = warp * 4 + j;
        int grow = (b * H_ + h) * N_ + n0 + r;
        float4 v[8];
        float mx = -1e30f;
#pragma unroll
        for (int i = 0; i < 8; i++) {
            v[i] = *reinterpret_cast<float4*>(&S[r * SSTRIDE + (i * 32 + lane) * 4]);
            mx = fmaxf(mx, fmaxf(fmaxf(v[i].x, v[i].y), fmaxf(v[i].z, v[i].w)));
        }
#pragma unroll
        for (int o = 16; o > 0; o >>= 1)
            mx = fmaxf(mx, __shfl_xor_sync(0xffffffffu, mx, o));
        float sum = 0.0f;
#pragma unroll
        for (int i = 0; i < 8; i++) {
            v[i].x = __expf(v[i].x - mx);
            v[i].y = __expf(v[i].y - mx);
            v[i].z = __expf(v[i].z - mx);
            v[i].w = __expf(v[i].w - mx);
            sum += (v[i].x + v[i].y) + (v[i].z + v[i].w);
        }
#pragma unroll
        for (int o = 16; o > 0; o >>= 1)
            sum += __shfl_xor_sync(0xffffffffu, sum, o);
        float inv = 1.0f / sum;
#pragma unroll
        for (int i = 0; i < 8; i++) {
            float4 p = make_float4(v[i].x * inv, v[i].y * inv, v[i].z * inv, v[i].w * inv);
            *reinterpret_cast<float4*>(probs + (size_t)grow * M_ + (i * 32 + lane) * 4) = p;
            uint4 q = make_uint4(f2tf(p.x), f2tf(p.y), f2tf(p.z), f2tf(p.w));
            *reinterpret_cast<uint4*>(&St[r * SSTRIDE + (i * 32 + lane) * 4]) = q;
        }
    }
    __syncthreads();

    // ---- phase 3: attn_out = P @ V, V tiles double-buffered ---------------------
    {
        const float* vsrc = g_V + (size_t)(b * M_) * C_ + h * 64;
#pragma unroll
        for (int i = 0; i < 4; i++) {
            int t = tid + i * 256;
            int r = t >> 4, c4 = t & 15;
            float4 v = *reinterpret_cast<const float4*>(vsrc + (size_t)r * C_ + c4 * 4);
            uint32_t* d = KV + r * KVSTRIDE + c4 * 4;
            d[0] = f2tf(v.x); d[1] = f2tf(v.y); d[2] = f2tf(v.z); d[3] = f2tf(v.w);
        }
        __syncthreads();

        float oacc[2][4] = {};
        for (int mt = 0; mt < 16; mt++) {
            if (mt < 15) {
                const float* s2 = vsrc + (size_t)((mt + 1) * 64) * C_;
                uint32_t* dst = KV + ((mt + 1) & 1) * KVBUF;
#pragma unroll
                for (int i = 0; i < 4; i++) {
                    int t = tid + i * 256;
                    int r = t >> 4, c4 = t & 15;
                    float4 v = *reinterpret_cast<const float4*>(s2 + (size_t)r * C_ + c4 * 4);
                    uint32_t* d = dst + r * KVSTRIDE + c4 * 4;
                    d[0] = f2tf(v.x); d[1] = f2tf(v.y); d[2] = f2tf(v.z); d[3] = f2tf(v.w);
                }
            }
            const uint32_t* Vb = KV + (mt & 1) * KVBUF;
            const int db = warp * 8;
#pragma unroll
            for (int ks = 0; ks < 8; ks++) {
                int kcol = mt * 64 + ks * 8;
                uint32_t aa[2][4], bb[2];
#pragma unroll
                for (int hf = 0; hf < 2; hf++) {
                    int rb = hf * 16;
                    aa[hf][0] = St[(rb + grp) * SSTRIDE + kcol + t4];
                    aa[hf][1] = St[(rb + 8 + grp) * SSTRIDE + kcol + t4];
                    aa[hf][2] = St[(rb + grp) * SSTRIDE + kcol + 4 + t4];
                    aa[hf][3] = St[(rb + 8 + grp) * SSTRIDE + kcol + 4 + t4];
                }
                bb[0] = Vb[(ks * 8 + t4) * KVSTRIDE + db + grp];
                bb[1] = Vb[(ks * 8 + 4 + t4) * KVSTRIDE + db + grp];
                mma8(oacc[0], aa[0], bb);
                mma8(oacc[1], aa[1], bb);
            }
            __syncthreads();
        }

#pragma unroll
        for (int hf = 0; hf < 2; hf++) {
            int r0 = n0 + hf * 16 + grp;
            int d = warp * 8 + 2 * t4;
            *reinterpret_cast<float2*>(
                g_AO + (size_t)(b * N_ + r0) * C_ + h * 64 + d) =
                make_float2(oacc[hf][0], oacc[hf][1]);
            *reinterpret_cast<float2*>(
                g_AO + (size_t)(b * N_ + r0 + 8) * C_ + h * 64 + d) =
                make_float2(oacc[hf][2], oacc[hf][3]);
        }
    }
}

// ---------------------------------- host ----------------------------------------
extern "C" void kernel_launch(void* const* d_in, const int* in_sizes, int n_in,
                              void* d_out, int out_size)
{
    const float* query  = (const float*)d_in[0];
    const float* key    = (const float*)d_in[1];
    const float* value  = (const float*)d_in[2];
    const float* Wq     = (const float*)d_in[3];
    const float* bq     = (const float*)d_in[4];
    const float* Wk     = (const float*)d_in[5];
    const float* bk     = (const float*)d_in[6];
    const float* Wv     = (const float*)d_in[7];
    const float* bv     = (const float*)d_in[8];
    const float* Wo     = (const float*)d_in[9];
    const float* bo     = (const float*)d_in[10];
    const float* lamlog = (const float*)d_in[11];
    float* out = (float*)d_out;

    float *qw, *kb, *vb, *ao, *pfb;
    cudaGetSymbolAddress((void**)&qw,  g_Qw);
    cudaGetSymbolAddress((void**)&kb,  g_K);
    cudaGetSymbolAddress((void**)&vb,  g_V);
    cudaGetSymbolAddress((void**)&ao,  g_AO);
    cudaGetSymbolAddress((void**)&pfb, g_probs_fb);

    cudaFuncSetAttribute(attn_fused,
                         cudaFuncAttributeMaxDynamicSharedMemorySize, SMEM_ATTN);

    const size_t out_elems  = (size_t)B_ * N_ * C_;
    const size_t prob_elems = (size_t)B_ * H_ * N_ * M_;
    float* probs = ((size_t)out_size >= out_elems + prob_elems)
                       ? (out + out_elems) : pfb;

    dim3 gproj(C_ / 128, (B_ * N_) / 128);  // (8, 16)

    // Q' = (query @ Wq + bq) * w_col(lambda);  K, V projections
    sgemm_tc<<<gproj, 256>>>(query, Wq, bq, qw, B_ * N_, C_, C_, 1, lamlog);
    sgemm_tc<<<gproj, 256>>>(key,   Wk, bk, kb, B_ * M_, C_, C_, 0, nullptr);
    sgemm_tc<<<gproj, 256>>>(value, Wv, bv, vb, B_ * M_, C_, C_, 0, nullptr);

    // fused: S = Q'K^T -> softmax -> probs -> attn_out = P @ V
    attn_fused<<<dim3(N_ / QROWS, H_, B_), 256, SMEM_ATTN>>>(probs);

    // output = attn_out @ Wo + bo
    sgemm_tc<<<gproj, 256>>>(ao, Wo, bo, out, B_ * N_, C_, C_, 0, nullptr);
}